// round 11
// baseline (speedup 1.0000x reference)
#include <cuda_runtime.h>
#include <cuda_bf16.h>
#include <math.h>
#include <stdint.h>

#ifndef M_PI
#define M_PI 3.14159265358979323846
#endif

#define DEPTH 5
#define HID 128
#define CODE_D 400
#define NFREQ 9
#define NB 8
#define NPTS 32768
#define TP 128
#define TOTAL_PTS (NB * NPTS)
#define NTHR 512

#define PZ 136   // bf16 pitch for 128-col tiles (Z, W)  -> 272 B/row
#define PY 24    // bf16 pitch for 16-col tiles (Y, F)   -> 48 B/row

// ---------------------------------------------------------------------------
// Device scratch
// ---------------------------------------------------------------------------
__device__ float g_code[DEPTH][NB][HID];
__device__ float g_norm[5][6];
__device__ __align__(16) __nv_bfloat16 g_wt[DEPTH][2][HID * PZ];      // hi/lo
__device__ __align__(16) __nv_bfloat16 g_ft[DEPTH + 1][2][HID * PY];  // hi/lo

// ---------------------------------------------------------------------------
// SMEM byte map (220,672 B)
// ---------------------------------------------------------------------------
#define SM_CBB   0            // 2 x 128 f32 ping-pong (code+bfwd)
#define SM_FBB   1024         // 2 x 128 f32 ping-pong (bftr)
#define SM_WOUT  2048
#define SM_OUTP  2560         // float[4][128]
#define SM_YS    4608         // 6*128*9 f32 = 27648
#define SM_ZH    32256        // 128*272 = 34816
#define SM_ZL    67072
#define SM_WH    101888
#define SM_WL    136704
#define SM_YB    171520       // 2 bufs x (H|L) = 24576
#define SM_FT    196096       // 2 bufs x (H|L) = 24576
#define SM_TOTAL 220672

#define YBSTRIDE 12288
#define HALFOFF  6144

// ---------------------------------------------------------------------------
// PTX helpers
// ---------------------------------------------------------------------------
__device__ __forceinline__ uint32_t smem_u32(const void* p) {
    uint32_t a;
    asm("{ .reg .u64 t; cvta.to.shared.u64 t, %1; cvt.u32.u64 %0, t; }"
        : "=r"(a) : "l"(p));
    return a;
}
__device__ __forceinline__ void ldsm4(uint32_t* r, uint32_t addr) {
    asm volatile("ldmatrix.sync.aligned.m8n8.x4.shared.b16 {%0,%1,%2,%3}, [%4];"
                 : "=r"(r[0]), "=r"(r[1]), "=r"(r[2]), "=r"(r[3]) : "r"(addr));
}
__device__ __forceinline__ void ldsm2(uint32_t* r, uint32_t addr) {
    asm volatile("ldmatrix.sync.aligned.m8n8.x2.shared.b16 {%0,%1}, [%2];"
                 : "=r"(r[0]), "=r"(r[1]) : "r"(addr));
}
__device__ __forceinline__ void mma16816(float* d, const uint32_t* a, const uint32_t* b) {
    asm volatile(
        "mma.sync.aligned.m16n8k16.row.col.f32.bf16.bf16.f32 "
        "{%0,%1,%2,%3}, {%4,%5,%6,%7}, {%8,%9}, {%0,%1,%2,%3};"
        : "+f"(d[0]), "+f"(d[1]), "+f"(d[2]), "+f"(d[3])
        : "r"(a[0]), "r"(a[1]), "r"(a[2]), "r"(a[3]), "r"(b[0]), "r"(b[1]));
}
__device__ __forceinline__ void split2(float z0, float z1, uint32_t& hi, uint32_t& lo) {
    uint32_t h;
    asm("cvt.rn.bf16x2.f32 %0, %1, %2;" : "=r"(h) : "f"(z1), "f"(z0));
    float h0 = __uint_as_float(h << 16);
    float h1 = __uint_as_float(h & 0xffff0000u);
    asm("cvt.rn.bf16x2.f32 %0, %1, %2;" : "=r"(lo) : "f"(z1 - h1), "f"(z0 - h0));
    hi = h;
}
__device__ __forceinline__ void cpa16(uint32_t dst, const void* src) {
    asm volatile("cp.async.cg.shared.global [%0], [%1], 16;" :: "r"(dst), "l"(src));
}
#define CP_COMMIT() asm volatile("cp.async.commit_group;" ::: "memory")
#define CP_WAIT(n)  asm volatile("cp.async.wait_group %0;" :: "n"(n) : "memory")

// ---------------------------------------------------------------------------
// Merged prep kernel
// ---------------------------------------------------------------------------
#define NCODE_BLK (DEPTH * NB * HID / 8)
#define WT_ELEMS (DEPTH * HID * PZ)
#define FT_ELEMS ((DEPTH + 1) * HID * PY)
#define NW_BLK ((WT_ELEMS + FT_ELEMS + 255) / 256)

__global__ void prep_all(const float* __restrict__ a,
                         const float* __restrict__ Wcode,
                         const float* __restrict__ bcode,
                         const float* __restrict__ Wfwd,
                         const float* __restrict__ Wftr) {
    int blk = blockIdx.x, tid = threadIdx.x;
    if (blk < NCODE_BLK) {
        int wid = tid >> 5, lane = tid & 31;
        int gw = blk * 8 + wid;
        int layer = gw >> 10;
        int rem = gw & 1023;
        int b = rem >> 7, h = rem & 127;
        const float* wc = Wcode + (size_t)(layer * HID + h) * CODE_D;
        const float* av = a + b * CODE_D;
        float s = 0.f;
        for (int c = lane; c < CODE_D; c += 32) s = fmaf(av[c], wc[c], s);
        #pragma unroll
        for (int o = 16; o > 0; o >>= 1) s += __shfl_xor_sync(0xffffffffu, s, o);
        if (lane == 0) g_code[layer][b][h] = s + bcode[layer * HID + h];
        if (blk == 0 && wid == 0 && lane < 30) {
            int am = lane / 6, sh = lane % 6, l = am + sh;
            double r = 1.0;
            for (int k = l - am + 1; k <= l + am; ++k) r /= (double)k;
            g_norm[am][sh] = (float)sqrt((2.0 * l + 1.0) / (4.0 * M_PI) * r);
        }
    } else {
        int i = (blk - NCODE_BLK) * 256 + tid;
        if (i < WT_ELEMS) {
            int l = i / (HID * PZ), r = i % (HID * PZ), g = r / PZ, c = r % PZ;
            float v = (c < HID) ? Wfwd[(l * HID + g) * HID + c] : 0.f;
            __nv_bfloat16 hi = __float2bfloat16(v);
            __nv_bfloat16 lo = __float2bfloat16(v - __bfloat162float(hi));
            g_wt[l][0][r] = hi;
            g_wt[l][1][r] = lo;
        } else if (i < WT_ELEMS + FT_ELEMS) {
            int j = i - WT_ELEMS;
            int s = j / (HID * PY), r = j % (HID * PY), h = r / PY, f = r % PY;
            float v = (f < NFREQ) ? Wftr[(s * HID + h) * NFREQ + f] : 0.f;
            __nv_bfloat16 hi = __float2bfloat16(v);
            __nv_bfloat16 lo = __float2bfloat16(v - __bfloat162float(hi));
            g_ft[s][0][r] = hi;
            g_ft[s][1][r] = lo;
        }
    }
}

// ---------------------------------------------------------------------------
// Main kernel: 512 threads, 4x4 warp grid (warp tile 32m x 32n)
// ---------------------------------------------------------------------------
__global__ __launch_bounds__(NTHR, 1)
void sinr_mma(const float* __restrict__ x,
              const float* __restrict__ bftr,
              const float* __restrict__ bfwd,
              const float* __restrict__ Wout,
              const float* __restrict__ bout,
              float* __restrict__ out) {
    extern __shared__ char smem[];
    const uint32_t sb = smem_u32(smem);
    const int tid = threadIdx.x, wid = tid >> 5, lane = tid & 31;
    const int blk = blockIdx.x, pt0 = blk * TP, b = blk >> 8;

    const int warpP = wid & 3, warpG = wid >> 2;
    const int m0w = warpP * 32, n0w = warpG * 32;

    // ---- prologue cp.async: F0->buf0 (g1), W0 (g2), F1->buf1 (g3) ----
    {
        const char* f0 = (const char*)g_ft[0];
        for (int i = tid; i < 768; i += NTHR)
            cpa16(sb + SM_FT + i * 16, f0 + i * 16);
        CP_COMMIT();
        const char* ws = (const char*)g_wt[0];
        for (int i = tid; i < 4352; i += NTHR)
            cpa16(sb + SM_WH + i * 16, ws + i * 16);
        CP_COMMIT();
        const char* f1 = (const char*)g_ft[1];
        for (int i = tid; i < 768; i += NTHR)
            cpa16(sb + SM_FT + YBSTRIDE + i * 16, f1 + i * 16);
        CP_COMMIT();
    }

    // ---- spherical harmonics into Ys (fp32), one point per thread ----
    if (tid < TP) {
        float theta = x[(pt0 + tid) * 2 + 0];
        float phi   = x[(pt0 + tid) * 2 + 1];
        float c = cosf(phi);
        float s2 = sqrtf(fmaxf(1.f - c * c, 0.f));
        float P[5][6];
        float pmm = 1.f;
        #pragma unroll
        for (int am = 0; am < 5; ++am) {
            if (am > 0) pmm *= -(2.f * am - 1.f) * s2;
            float p0 = pmm;
            P[am][0] = p0;
            float p1 = c * (2.f * am + 1.f) * pmm;
            P[am][1] = p1;
            #pragma unroll
            for (int sh = 2; sh < 6; ++sh) {
                int l = am + sh;
                float pl = ((2.f * l - 1.f) * c * p1 - (l + am - 1.f) * p0) * (1.f / (float)sh);
                p0 = p1; p1 = pl;
                P[am][sh] = pl;
            }
        }
        float ck[5], sk[5], c1, s1;
        sincosf(theta, &s1, &c1);
        ck[0] = 1.f; sk[0] = 0.f;
        ck[1] = c1;  sk[1] = s1;
        #pragma unroll
        for (int m = 2; m < 5; ++m) {
            ck[m] = c1 * ck[m - 1] - s1 * sk[m - 1];
            sk[m] = s1 * ck[m - 1] + c1 * sk[m - 1];
        }
        const float SQ2 = 1.41421356237309515f;
        float* Ys = (float*)(smem + SM_YS);
        #pragma unroll
        for (int s = 0; s < 6; ++s) {
            float* yrow = &Ys[(s * TP + tid) * NFREQ];
            yrow[4] = g_norm[0][s] * P[0][s];
            #pragma unroll
            for (int am = 1; am < 5; ++am) {
                float base = SQ2 * g_norm[am][s] * P[am][s];
                if (am & 1) base = -base;
                yrow[4 + am] = base * ck[am];
                yrow[4 - am] = base * sk[am];
            }
        }
    }

    // ---- spread Y split: 384 threads, row = tid/3, 3 freqs per thread ----
    #define SPLIT_Y_SPREAD(s, buf)                                               \
        if (tid < 384) {                                                         \
            int row_ = tid / 3, ch_ = tid - row_ * 3;                            \
            const float* yr = (const float*)(smem + SM_YS) + ((s) * TP + row_) * NFREQ; \
            __nv_bfloat16* yh = (__nv_bfloat16*)(smem + SM_YB + (buf) * YBSTRIDE) + row_ * PY; \
            __nv_bfloat16* yl = (__nv_bfloat16*)(smem + SM_YB + (buf) * YBSTRIDE + HALFOFF) + row_ * PY; \
            _Pragma("unroll")                                                    \
            for (int q = 0; q < 3; ++q) {                                        \
                int f = ch_ * 3 + q;                                             \
                float v = yr[f];                                                 \
                __nv_bfloat16 h = __float2bfloat16(v);                           \
                yh[f] = h;                                                       \
                yl[f] = __float2bfloat16(v - __bfloat162float(h));               \
            }                                                                    \
        }

    __syncthreads();   // publish YS before cross-thread spread splits

    // ---- init staging: biases, wout, zero Y pads; spread Y0/Y1 splits ----
    if (tid < TP) {
        ((float*)(smem + SM_FBB))[tid] = bftr[tid];
        ((float*)(smem + SM_FBB))[TP + tid] = bftr[HID + tid];
        ((float*)(smem + SM_CBB))[tid] = g_code[0][b][tid] + bfwd[tid];
        ((float*)(smem + SM_WOUT))[tid] = Wout[tid];
        #pragma unroll
        for (int bu = 0; bu < 2; ++bu) {
            __nv_bfloat16* yh = (__nv_bfloat16*)(smem + SM_YB + bu * YBSTRIDE) + tid * PY;
            __nv_bfloat16* yl = (__nv_bfloat16*)(smem + SM_YB + bu * YBSTRIDE + HALFOFF) + tid * PY;
            #pragma unroll
            for (int f = NFREQ; f < 16; ++f) { yh[f] = __float2bfloat16(0.f); yl[f] = __float2bfloat16(0.f); }
        }
    }
    SPLIT_Y_SPREAD(0, 0);
    SPLIT_Y_SPREAD(1, 1);
    CP_WAIT(0);      // F0, W0, F1 all landed
    __syncthreads();

    // lane address components
    const uint32_t aRow = (uint32_t)(lane & 15);
    const uint32_t aK8  = (uint32_t)((lane >> 4) * 8);
    const uint32_t bRow = (uint32_t)((lane & 7) + ((lane >> 4) & 1) * 8);
    const uint32_t bK8  = (uint32_t)(((lane >> 3) & 1) * 8);
    const uint32_t fRow = (uint32_t)(lane & 7);
    const uint32_t fK8  = (uint32_t)(((lane >> 3) & 1) * 8);

    const float* wos = (const float*)(smem + SM_WOUT);
    const int eRow = lane >> 2;
    const int eCol = (lane & 3) * 2;

    float fa[2][4][4];     // feature MMA results (seeded with fb) for next epilogue
    float os[4] = {0.f, 0.f, 0.f, 0.f};

    // ---- init: z0 = fb0 + Y0*F0^T -> Z;  then fa (seeded fb1) for layer 0 ----
    {
        const float* fb = (const float*)(smem + SM_FBB);   // buf0
        uint32_t Yh[2][4], Yl[2][4];
        #pragma unroll
        for (int mt = 0; mt < 2; ++mt) {
            uint32_t ro = (uint32_t)(m0w + mt * 16 + (int)aRow) * 48 + aK8 * 2;
            ldsm4(Yh[mt], sb + SM_YB + ro);
            ldsm4(Yl[mt], sb + SM_YB + HALFOFF + ro);
        }
        #pragma unroll
        for (int nt = 0; nt < 4; ++nt) {
            uint32_t fo = (uint32_t)(n0w + nt * 8 + (int)fRow) * 48 + fK8 * 2;
            uint32_t Fh[2], Fl[2];
            ldsm2(Fh, sb + SM_FT + fo);
            ldsm2(Fl, sb + SM_FT + HALFOFF + fo);
            int c0 = n0w + nt * 8 + eCol;
            float2 fbv = *(const float2*)&fb[c0];
            #pragma unroll
            for (int mt = 0; mt < 2; ++mt) {
                float t4[4] = {fbv.x, fbv.y, fbv.x, fbv.y};
                mma16816(t4, Yh[mt], Fh);
                mma16816(t4, Yh[mt], Fl);
                mma16816(t4, Yl[mt], Fh);
                int r0 = m0w + mt * 16 + eRow;
                uint32_t hi, lo;
                uint32_t o0 = (uint32_t)(r0 * 272 + c0 * 2);
                uint32_t o1 = o0 + 8 * 272;
                split2(t4[0], t4[1], hi, lo);
                *(uint32_t*)(smem + SM_ZH + o0) = hi;
                *(uint32_t*)(smem + SM_ZL + o0) = lo;
                split2(t4[2], t4[3], hi, lo);
                *(uint32_t*)(smem + SM_ZH + o1) = hi;
                *(uint32_t*)(smem + SM_ZL + o1) = lo;
            }
        }
        // fa for layer 0 = shift 1 tiles (buf 1), seeded with fb1
        const float* fb1 = (const float*)(smem + SM_FBB) + TP;
        #pragma unroll
        for (int mt = 0; mt < 2; ++mt) {
            uint32_t ro = (uint32_t)(m0w + mt * 16 + (int)aRow) * 48 + aK8 * 2;
            ldsm4(Yh[mt], sb + SM_YB + YBSTRIDE + ro);
            ldsm4(Yl[mt], sb + SM_YB + YBSTRIDE + HALFOFF + ro);
        }
        #pragma unroll
        for (int nt = 0; nt < 4; ++nt) {
            uint32_t fo = (uint32_t)(n0w + nt * 8 + (int)fRow) * 48 + fK8 * 2;
            uint32_t Fh[2], Fl[2];
            ldsm2(Fh, sb + SM_FT + YBSTRIDE + fo);
            ldsm2(Fl, sb + SM_FT + YBSTRIDE + HALFOFF + fo);
            int c0 = n0w + nt * 8 + eCol;
            float2 fbv = *(const float2*)&fb1[c0];
            #pragma unroll
            for (int mt = 0; mt < 2; ++mt) {
                fa[mt][nt][0] = fbv.x; fa[mt][nt][1] = fbv.y;
                fa[mt][nt][2] = fbv.x; fa[mt][nt][3] = fbv.y;
                mma16816(fa[mt][nt], Yh[mt], Fh);
                mma16816(fa[mt][nt], Yh[mt], Fl);
                mma16816(fa[mt][nt], Yl[mt], Fh);
            }
        }
    }
    __syncthreads();

    // =========================== 5 fused layers =============================
    #pragma unroll 1
    for (int l = 0; l < DEPTH; ++l) {
        const int sbuf = l & 1;   // buffer for shift l+2 (staged now, fa'd at E2)

        // ---- A: stage shift l+2 F tiles + biases + Y split (no barrier) ----
        if (l <= 3) {
            const char* fs = (const char*)g_ft[l + 2];
            for (int i = tid; i < 768; i += NTHR)
                cpa16(sb + SM_FT + sbuf * YBSTRIDE + i * 16, fs + i * 16);
        }
        CP_COMMIT();
        if (l <= 3) {
            SPLIT_Y_SPREAD(l + 2, sbuf);
            if (tid >= 384 && tid < 384 + TP) {
                int t = tid - 384;
                ((float*)(smem + SM_FBB))[sbuf * TP + t] = bftr[(l + 2) * HID + t];
                ((float*)(smem + SM_CBB))[((l + 1) & 1) * TP + t] =
                    g_code[l + 1][b][t] + bfwd[(l + 1) * HID + t];
            }
        }

        // ---- B: main GEMM (3-term split), acc seeded with cb ----
        float acc[2][4][4];
        {
            const float* cbp = (const float*)(smem + SM_CBB) + (l & 1) * TP;
            #pragma unroll
            for (int nt = 0; nt < 4; ++nt) {
                float2 cbv = *(const float2*)&cbp[n0w + nt * 8 + eCol];
                #pragma unroll
                for (int mt = 0; mt < 2; ++mt) {
                    acc[mt][nt][0] = cbv.x; acc[mt][nt][1] = cbv.y;
                    acc[mt][nt][2] = cbv.x; acc[mt][nt][3] = cbv.y;
                }
            }
        }

        #pragma unroll
        for (int ks = 0; ks < 8; ++ks) {
            const uint32_t k0 = ks * 16;
            uint32_t Ah[2][4], Al[2][4];
            #pragma unroll
            for (int mt = 0; mt < 2; ++mt) {
                uint32_t ro = (uint32_t)(m0w + mt * 16 + (int)aRow) * 272 + (k0 + aK8) * 2;
                ldsm4(Ah[mt], sb + SM_ZH + ro);
                ldsm4(Al[mt], sb + SM_ZL + ro);
            }
            #pragma unroll
            for (int np = 0; np < 2; ++np) {
                uint32_t ro = (uint32_t)(n0w + np * 16 + (int)bRow) * 272 + (k0 + bK8) * 2;
                uint32_t t[4];
                ldsm4(t, sb + SM_WH + ro);
                #pragma unroll
                for (int mt = 0; mt < 2; ++mt) {
                    mma16816(acc[mt][np * 2],     Ah[mt], t);
                    mma16816(acc[mt][np * 2 + 1], Ah[mt], t + 2);
                    mma16816(acc[mt][np * 2],     Al[mt], t);
                    mma16816(acc[mt][np * 2 + 1], Al[mt], t + 2);
                }
                ldsm4(t, sb + SM_WL + ro);
                #pragma unroll
                for (int mt = 0; mt < 2; ++mt) {
                    mma16816(acc[mt][np * 2],     Ah[mt], t);
                    mma16816(acc[mt][np * 2 + 1], Ah[mt], t + 2);
                }
            }
        }

        // ---- C: F[l+2] landed + all Z/W reads done ----
        CP_WAIT(0);
        __syncthreads();

        // ---- D: prefetch W[l+1] ----
        if (l + 1 < DEPTH) {
            const char* ws = (const char*)g_wt[l + 1];
            for (int i = tid; i < 4352; i += NTHR)
                cpa16(sb + SM_WH + i * 16, ws + i * 16);
        }
        CP_COMMIT();

        // ---- E: epilogue combine: z = acc * fa (biases pre-folded) ----
        {
            #pragma unroll
            for (int mt = 0; mt < 2; ++mt)
                #pragma unroll
                for (int nt = 0; nt < 4; ++nt) {
                    int c0 = n0w + nt * 8 + eCol;
                    int r0 = m0w + mt * 16 + eRow;
                    float z0 = acc[mt][nt][0] * fa[mt][nt][0];
                    float z1 = acc[mt][nt][1] * fa[mt][nt][1];
                    float z2 = acc[mt][nt][2] * fa[mt][nt][2];
                    float z3 = acc[mt][nt][3] * fa[mt][nt][3];
                    if (l < DEPTH - 1) {
                        uint32_t hi, lo;
                        uint32_t o0 = (uint32_t)(r0 * 272 + c0 * 2);
                        uint32_t o1 = o0 + 8 * 272;
                        split2(z0, z1, hi, lo);
                        *(uint32_t*)(smem + SM_ZH + o0) = hi;
                        *(uint32_t*)(smem + SM_ZL + o0) = lo;
                        split2(z2, z3, hi, lo);
                        *(uint32_t*)(smem + SM_ZH + o1) = hi;
                        *(uint32_t*)(smem + SM_ZL + o1) = lo;
                    } else {
                        float2 wv = *(const float2*)&wos[c0];
                        os[mt * 2 + 0] = fmaf(z0, wv.x, fmaf(z1, wv.y, os[mt * 2 + 0]));
                        os[mt * 2 + 1] = fmaf(z2, wv.x, fmaf(z3, wv.y, os[mt * 2 + 1]));
                    }
                }
        }

        // ---- E2: compute fa for next layer (shift l+2, buf sbuf), seeded fb --
        if (l < DEPTH - 1) {
            uint32_t Yh[2][4], Yl[2][4];
            uint32_t yb = sb + SM_YB + sbuf * YBSTRIDE;
            uint32_t ft = sb + SM_FT + sbuf * YBSTRIDE;
            const float* fbp2 = (const float*)(smem + SM_FBB) + sbuf * TP;
            #pragma unroll
            for (int mt = 0; mt < 2; ++mt) {
                uint32_t ro = (uint32_t)(m0w + mt * 16 + (int)aRow) * 48 + aK8 * 2;
                ldsm4(Yh[mt], yb + ro);
                ldsm4(Yl[mt], yb + HALFOFF + ro);
            }
            #pragma unroll
            for (int nt = 0; nt < 4; ++nt) {
                uint32_t fo = (uint32_t)(n0w + nt * 8 + (int)fRow) * 48 + fK8 * 2;
                uint32_t Fh[2], Fl[2];
                ldsm2(Fh, ft + fo);
                ldsm2(Fl, ft + HALFOFF + fo);
                float2 fbv = *(const float2*)&fbp2[n0w + nt * 8 + eCol];
                #pragma unroll
                for (int mt = 0; mt < 2; ++mt) {
                    fa[mt][nt][0] = fbv.x; fa[mt][nt][1] = fbv.y;
                    fa[mt][nt][2] = fbv.x; fa[mt][nt][3] = fbv.y;
                    mma16816(fa[mt][nt], Yh[mt], Fh);
                    mma16816(fa[mt][nt], Yh[mt], Fl);
                    mma16816(fa[mt][nt], Yl[mt], Fh);
                }
            }
        }

        // ---- G: W[l+1] landed; publish Z/buffers ----
        CP_WAIT(0);
        __syncthreads();
    }

    // ---- output reduce: 4 warpG partials ----
    {
        #pragma unroll
        for (int i = 0; i < 4; ++i) {
            os[i] += __shfl_xor_sync(0xffffffffu, os[i], 1);
            os[i] += __shfl_xor_sync(0xffffffffu, os[i], 2);
        }
        float* outp = (float*)(smem + SM_OUTP);
        if ((lane & 3) == 0) {
            #pragma unroll
            for (int mt = 0; mt < 2; ++mt) {
                outp[warpG * TP + m0w + mt * 16 + eRow]     = os[mt * 2 + 0];
                outp[warpG * TP + m0w + mt * 16 + 8 + eRow] = os[mt * 2 + 1];
            }
        }
        __syncthreads();
        if (tid < TP)
            out[pt0 + tid] = outp[tid] + outp[TP + tid] + outp[2 * TP + tid] +
                             outp[3 * TP + tid] + *bout;
    }
}

// ---------------------------------------------------------------------------
extern "C" void kernel_launch(void* const* d_in, const int* in_sizes, int n_in,
                              void* d_out, int out_size) {
    const float* x     = (const float*)d_in[0];
    const float* a     = (const float*)d_in[1];
    const float* Wftr  = (const float*)d_in[2];
    const float* bftr  = (const float*)d_in[3];
    const float* Wfwd  = (const float*)d_in[4];
    const float* bfwd  = (const float*)d_in[5];
    const float* Wcode = (const float*)d_in[6];
    const float* bcode = (const float*)d_in[7];
    const float* Wout  = (const float*)d_in[8];
    const float* bout  = (const float*)d_in[9];
    float* out = (float*)d_out;

    prep_all<<<NCODE_BLK + NW_BLK, 256>>>(a, Wcode, bcode, Wfwd, Wftr);

    cudaFuncSetAttribute(sinr_mma, cudaFuncAttributeMaxDynamicSharedMemorySize,
                         SM_TOTAL);
    sinr_mma<<<TOTAL_PTS / TP, NTHR, SM_TOTAL>>>(x, bftr, bfwd, Wout, bout, out);

    if (out_size >= TOTAL_PTS + in_sizes[0]) {
        cudaMemcpyAsync(out + TOTAL_PTS, x, (size_t)in_sizes[0] * sizeof(float),
                        cudaMemcpyDeviceToDevice);
    }
}

// round 12
// speedup vs baseline: 1.0324x; 1.0324x over previous
#include <cuda_runtime.h>
#include <cuda_bf16.h>
#include <math.h>
#include <stdint.h>

#ifndef M_PI
#define M_PI 3.14159265358979323846
#endif

#define DEPTH 5
#define HID 128
#define CODE_D 400
#define NFREQ 9
#define NB 8
#define NPTS 32768
#define TP 128
#define TOTAL_PTS (NB * NPTS)
#define NTHR 512

#define PZ 136   // bf16 pitch for 128-col tiles (Z, W)  -> 272 B/row
#define PY 24    // bf16 pitch for 16-col tiles (Y, F)   -> 48 B/row

// ---------------------------------------------------------------------------
// Device scratch
// ---------------------------------------------------------------------------
__device__ float g_code[DEPTH][NB][HID];
__device__ float g_norm[5][6];
__device__ __align__(16) __nv_bfloat16 g_wt[DEPTH][2][HID * PZ];      // hi/lo
__device__ __align__(16) __nv_bfloat16 g_ft[DEPTH + 1][2][HID * PY];  // hi/lo

// ---------------------------------------------------------------------------
// SMEM byte map (220,672 B)
// ---------------------------------------------------------------------------
#define SM_CBB   0            // 2 x 128 f32 ping-pong (code+bfwd)
#define SM_FBB   1024         // 2 x 128 f32 ping-pong (bftr)
#define SM_WOUT  2048
#define SM_OUTP  2560         // float[4][128]
#define SM_YS    4608         // 6*128*9 f32 = 27648
#define SM_ZH    32256        // 128*272 = 34816
#define SM_ZL    67072
#define SM_WH    101888
#define SM_WL    136704
#define SM_YB    171520       // 2 bufs x (H|L) = 24576
#define SM_FT    196096       // 2 bufs x (H|L) = 24576
#define SM_TOTAL 220672

#define YBSTRIDE 12288
#define HALFOFF  6144

// ---------------------------------------------------------------------------
// PTX helpers
// ---------------------------------------------------------------------------
__device__ __forceinline__ uint32_t smem_u32(const void* p) {
    uint32_t a;
    asm("{ .reg .u64 t; cvta.to.shared.u64 t, %1; cvt.u32.u64 %0, t; }"
        : "=r"(a) : "l"(p));
    return a;
}
__device__ __forceinline__ void ldsm4(uint32_t* r, uint32_t addr) {
    asm volatile("ldmatrix.sync.aligned.m8n8.x4.shared.b16 {%0,%1,%2,%3}, [%4];"
                 : "=r"(r[0]), "=r"(r[1]), "=r"(r[2]), "=r"(r[3]) : "r"(addr));
}
__device__ __forceinline__ void ldsm2(uint32_t* r, uint32_t addr) {
    asm volatile("ldmatrix.sync.aligned.m8n8.x2.shared.b16 {%0,%1}, [%2];"
                 : "=r"(r[0]), "=r"(r[1]) : "r"(addr));
}
__device__ __forceinline__ void mma16816(float* d, const uint32_t* a, const uint32_t* b) {
    asm volatile(
        "mma.sync.aligned.m16n8k16.row.col.f32.bf16.bf16.f32 "
        "{%0,%1,%2,%3}, {%4,%5,%6,%7}, {%8,%9}, {%0,%1,%2,%3};"
        : "+f"(d[0]), "+f"(d[1]), "+f"(d[2]), "+f"(d[3])
        : "r"(a[0]), "r"(a[1]), "r"(a[2]), "r"(a[3]), "r"(b[0]), "r"(b[1]));
}
__device__ __forceinline__ void split2(float z0, float z1, uint32_t& hi, uint32_t& lo) {
    uint32_t h;
    asm("cvt.rn.bf16x2.f32 %0, %1, %2;" : "=r"(h) : "f"(z1), "f"(z0));
    float h0 = __uint_as_float(h << 16);
    float h1 = __uint_as_float(h & 0xffff0000u);
    asm("cvt.rn.bf16x2.f32 %0, %1, %2;" : "=r"(lo) : "f"(z1 - h1), "f"(z0 - h0));
    hi = h;
}
__device__ __forceinline__ void cpa16(uint32_t dst, const void* src) {
    asm volatile("cp.async.cg.shared.global [%0], [%1], 16;" :: "r"(dst), "l"(src));
}
#define CP_COMMIT() asm volatile("cp.async.commit_group;" ::: "memory")
#define CP_WAIT(n)  asm volatile("cp.async.wait_group %0;" :: "n"(n) : "memory")

// ---------------------------------------------------------------------------
// Merged prep kernel
// ---------------------------------------------------------------------------
#define NCODE_BLK (DEPTH * NB * HID / 8)
#define WT_ELEMS (DEPTH * HID * PZ)
#define FT_ELEMS ((DEPTH + 1) * HID * PY)
#define NW_BLK ((WT_ELEMS + FT_ELEMS + 255) / 256)

__global__ void prep_all(const float* __restrict__ a,
                         const float* __restrict__ Wcode,
                         const float* __restrict__ bcode,
                         const float* __restrict__ Wfwd,
                         const float* __restrict__ Wftr) {
    int blk = blockIdx.x, tid = threadIdx.x;
    if (blk < NCODE_BLK) {
        int wid = tid >> 5, lane = tid & 31;
        int gw = blk * 8 + wid;
        int layer = gw >> 10;
        int rem = gw & 1023;
        int b = rem >> 7, h = rem & 127;
        const float* wc = Wcode + (size_t)(layer * HID + h) * CODE_D;
        const float* av = a + b * CODE_D;
        float s = 0.f;
        for (int c = lane; c < CODE_D; c += 32) s = fmaf(av[c], wc[c], s);
        #pragma unroll
        for (int o = 16; o > 0; o >>= 1) s += __shfl_xor_sync(0xffffffffu, s, o);
        if (lane == 0) g_code[layer][b][h] = s + bcode[layer * HID + h];
        if (blk == 0 && wid == 0 && lane < 30) {
            int am = lane / 6, sh = lane % 6, l = am + sh;
            double r = 1.0;
            for (int k = l - am + 1; k <= l + am; ++k) r /= (double)k;
            g_norm[am][sh] = (float)sqrt((2.0 * l + 1.0) / (4.0 * M_PI) * r);
        }
    } else {
        int i = (blk - NCODE_BLK) * 256 + tid;
        if (i < WT_ELEMS) {
            int l = i / (HID * PZ), r = i % (HID * PZ), g = r / PZ, c = r % PZ;
            float v = (c < HID) ? Wfwd[(l * HID + g) * HID + c] : 0.f;
            __nv_bfloat16 hi = __float2bfloat16(v);
            __nv_bfloat16 lo = __float2bfloat16(v - __bfloat162float(hi));
            g_wt[l][0][r] = hi;
            g_wt[l][1][r] = lo;
        } else if (i < WT_ELEMS + FT_ELEMS) {
            int j = i - WT_ELEMS;
            int s = j / (HID * PY), r = j % (HID * PY), h = r / PY, f = r % PY;
            float v = (f < NFREQ) ? Wftr[(s * HID + h) * NFREQ + f] : 0.f;
            __nv_bfloat16 hi = __float2bfloat16(v);
            __nv_bfloat16 lo = __float2bfloat16(v - __bfloat162float(hi));
            g_ft[s][0][r] = hi;
            g_ft[s][1][r] = lo;
        }
    }
}

// ---------------------------------------------------------------------------
// Main kernel: 512 threads, 4x4 warp grid (warp tile 32m x 32n)
// ---------------------------------------------------------------------------
__global__ __launch_bounds__(NTHR, 1)
void sinr_mma(const float* __restrict__ x,
              const float* __restrict__ bftr,
              const float* __restrict__ bfwd,
              const float* __restrict__ Wout,
              const float* __restrict__ bout,
              float* __restrict__ out) {
    extern __shared__ char smem[];
    const uint32_t sb = smem_u32(smem);
    const int tid = threadIdx.x, wid = tid >> 5, lane = tid & 31;
    const int blk = blockIdx.x, pt0 = blk * TP, b = blk >> 8;

    const int warpP = wid & 3, warpG = wid >> 2;
    const int m0w = warpP * 32, n0w = warpG * 32;

    // ---- prologue cp.async: F0->buf0 (g1), W0 (g2), F1->buf1 (g3) ----
    {
        const char* f0 = (const char*)g_ft[0];
        for (int i = tid; i < 768; i += NTHR)
            cpa16(sb + SM_FT + i * 16, f0 + i * 16);
        CP_COMMIT();
        const char* ws = (const char*)g_wt[0];
        for (int i = tid; i < 4352; i += NTHR)
            cpa16(sb + SM_WH + i * 16, ws + i * 16);
        CP_COMMIT();
        const char* f1 = (const char*)g_ft[1];
        for (int i = tid; i < 768; i += NTHR)
            cpa16(sb + SM_FT + YBSTRIDE + i * 16, f1 + i * 16);
        CP_COMMIT();
    }

    // ---- spherical harmonics into Ys (fp32), one point per thread ----
    if (tid < TP) {
        float theta = x[(pt0 + tid) * 2 + 0];
        float phi   = x[(pt0 + tid) * 2 + 1];
        float c = cosf(phi);
        float s2 = sqrtf(fmaxf(1.f - c * c, 0.f));
        float P[5][6];
        float pmm = 1.f;
        #pragma unroll
        for (int am = 0; am < 5; ++am) {
            if (am > 0) pmm *= -(2.f * am - 1.f) * s2;
            float p0 = pmm;
            P[am][0] = p0;
            float p1 = c * (2.f * am + 1.f) * pmm;
            P[am][1] = p1;
            #pragma unroll
            for (int sh = 2; sh < 6; ++sh) {
                int l = am + sh;
                float pl = ((2.f * l - 1.f) * c * p1 - (l + am - 1.f) * p0) * (1.f / (float)sh);
                p0 = p1; p1 = pl;
                P[am][sh] = pl;
            }
        }
        float ck[5], sk[5], c1, s1;
        sincosf(theta, &s1, &c1);
        ck[0] = 1.f; sk[0] = 0.f;
        ck[1] = c1;  sk[1] = s1;
        #pragma unroll
        for (int m = 2; m < 5; ++m) {
            ck[m] = c1 * ck[m - 1] - s1 * sk[m - 1];
            sk[m] = s1 * ck[m - 1] + c1 * sk[m - 1];
        }
        const float SQ2 = 1.41421356237309515f;
        float* Ys = (float*)(smem + SM_YS);
        #pragma unroll
        for (int s = 0; s < 6; ++s) {
            float* yrow = &Ys[(s * TP + tid) * NFREQ];
            yrow[4] = g_norm[0][s] * P[0][s];
            #pragma unroll
            for (int am = 1; am < 5; ++am) {
                float base = SQ2 * g_norm[am][s] * P[am][s];
                if (am & 1) base = -base;
                yrow[4 + am] = base * ck[am];
                yrow[4 - am] = base * sk[am];
            }
        }
    }

    // ---- Y split macro: shift s -> YB buffer buf (tid-local YS reads) ----
    #define SPLIT_Y(s, buf)                                                      \
        {                                                                        \
            const float* yr = (const float*)(smem + SM_YS) + ((s) * TP + tid) * NFREQ; \
            __nv_bfloat16* yh = (__nv_bfloat16*)(smem + SM_YB + (buf) * YBSTRIDE) + tid * PY; \
            __nv_bfloat16* yl = (__nv_bfloat16*)(smem + SM_YB + (buf) * YBSTRIDE + HALFOFF) + tid * PY; \
            _Pragma("unroll")                                                    \
            for (int f = 0; f < NFREQ; ++f) {                                    \
                float v = yr[f];                                                 \
                __nv_bfloat16 h = __float2bfloat16(v);                           \
                yh[f] = h;                                                       \
                yl[f] = __float2bfloat16(v - __bfloat162float(h));               \
            }                                                                    \
        }

    // ---- init staging: biases, wout, zero Y pads, Y0/Y1 splits ----
    if (tid < TP) {
        ((float*)(smem + SM_FBB))[tid] = bftr[tid];
        ((float*)(smem + SM_FBB))[TP + tid] = bftr[HID + tid];
        ((float*)(smem + SM_CBB))[tid] = g_code[0][b][tid] + bfwd[tid];
        ((float*)(smem + SM_WOUT))[tid] = Wout[tid];
        #pragma unroll
        for (int bu = 0; bu < 2; ++bu) {
            __nv_bfloat16* yh = (__nv_bfloat16*)(smem + SM_YB + bu * YBSTRIDE) + tid * PY;
            __nv_bfloat16* yl = (__nv_bfloat16*)(smem + SM_YB + bu * YBSTRIDE + HALFOFF) + tid * PY;
            #pragma unroll
            for (int f = NFREQ; f < 16; ++f) { yh[f] = __float2bfloat16(0.f); yl[f] = __float2bfloat16(0.f); }
        }
        SPLIT_Y(0, 0);
        SPLIT_Y(1, 1);
    }
    CP_WAIT(0);      // F0, W0, F1 all landed
    __syncthreads();

    // lane address components
    const uint32_t aRow = (uint32_t)(lane & 15);
    const uint32_t aK8  = (uint32_t)((lane >> 4) * 8);
    const uint32_t bRow = (uint32_t)((lane & 7) + ((lane >> 4) & 1) * 8);
    const uint32_t bK8  = (uint32_t)(((lane >> 3) & 1) * 8);
    const uint32_t fRow = (uint32_t)(lane & 7);
    const uint32_t fK8  = (uint32_t)(((lane >> 3) & 1) * 8);

    const float* wos = (const float*)(smem + SM_WOUT);
    const int eRow = lane >> 2;
    const int eCol = (lane & 3) * 2;

    float fa[2][4][4];     // feature MMA results (seeded with fb) for the epilogue
    float os[4] = {0.f, 0.f, 0.f, 0.f};

    // ---- init: z0 = fb0 + Y0*F0^T -> Z;  then fa (seeded fb1) for layer 0 ----
    {
        const float* fb = (const float*)(smem + SM_FBB);   // buf0
        uint32_t Yh[2][4], Yl[2][4];
        #pragma unroll
        for (int mt = 0; mt < 2; ++mt) {
            uint32_t ro = (uint32_t)(m0w + mt * 16 + (int)aRow) * 48 + aK8 * 2;
            ldsm4(Yh[mt], sb + SM_YB + ro);
            ldsm4(Yl[mt], sb + SM_YB + HALFOFF + ro);
        }
        #pragma unroll
        for (int nt = 0; nt < 4; ++nt) {
            uint32_t fo = (uint32_t)(n0w + nt * 8 + (int)fRow) * 48 + fK8 * 2;
            uint32_t Fh[2], Fl[2];
            ldsm2(Fh, sb + SM_FT + fo);
            ldsm2(Fl, sb + SM_FT + HALFOFF + fo);
            int c0 = n0w + nt * 8 + eCol;
            float2 fbv = *(const float2*)&fb[c0];
            #pragma unroll
            for (int mt = 0; mt < 2; ++mt) {
                float t4[4] = {fbv.x, fbv.y, fbv.x, fbv.y};
                mma16816(t4, Yh[mt], Fh);
                mma16816(t4, Yh[mt], Fl);
                mma16816(t4, Yl[mt], Fh);
                int r0 = m0w + mt * 16 + eRow;
                uint32_t hi, lo;
                uint32_t o0 = (uint32_t)(r0 * 272 + c0 * 2);
                uint32_t o1 = o0 + 8 * 272;
                split2(t4[0], t4[1], hi, lo);
                *(uint32_t*)(smem + SM_ZH + o0) = hi;
                *(uint32_t*)(smem + SM_ZL + o0) = lo;
                split2(t4[2], t4[3], hi, lo);
                *(uint32_t*)(smem + SM_ZH + o1) = hi;
                *(uint32_t*)(smem + SM_ZL + o1) = lo;
            }
        }
        // fa for layer 0 = shift 1 tiles (buf 1), seeded with fb1
        const float* fb1 = (const float*)(smem + SM_FBB) + TP;
        #pragma unroll
        for (int mt = 0; mt < 2; ++mt) {
            uint32_t ro = (uint32_t)(m0w + mt * 16 + (int)aRow) * 48 + aK8 * 2;
            ldsm4(Yh[mt], sb + SM_YB + YBSTRIDE + ro);
            ldsm4(Yl[mt], sb + SM_YB + YBSTRIDE + HALFOFF + ro);
        }
        #pragma unroll
        for (int nt = 0; nt < 4; ++nt) {
            uint32_t fo = (uint32_t)(n0w + nt * 8 + (int)fRow) * 48 + fK8 * 2;
            uint32_t Fh[2], Fl[2];
            ldsm2(Fh, sb + SM_FT + YBSTRIDE + fo);
            ldsm2(Fl, sb + SM_FT + YBSTRIDE + HALFOFF + fo);
            int c0 = n0w + nt * 8 + eCol;
            float2 fbv = *(const float2*)&fb1[c0];
            #pragma unroll
            for (int mt = 0; mt < 2; ++mt) {
                fa[mt][nt][0] = fbv.x; fa[mt][nt][1] = fbv.y;
                fa[mt][nt][2] = fbv.x; fa[mt][nt][3] = fbv.y;
                mma16816(fa[mt][nt], Yh[mt], Fh);
                mma16816(fa[mt][nt], Yh[mt], Fl);
                mma16816(fa[mt][nt], Yl[mt], Fh);
            }
        }
    }
    __syncthreads();

    // =========================== 5 fused layers =============================
    #pragma unroll 1
    for (int l = 0; l < DEPTH; ++l) {
        const int sbuf = l & 1;   // buffer for shift l+2 (staged now, fa'd at E2)

        // ---- A: stage shift l+2 F tiles + biases + Y split (no barrier) ----
        if (l <= 3) {
            const char* fs = (const char*)g_ft[l + 2];
            for (int i = tid; i < 768; i += NTHR)
                cpa16(sb + SM_FT + sbuf * YBSTRIDE + i * 16, fs + i * 16);
        }
        CP_COMMIT();
        if (tid < TP && l <= 3) {
            ((float*)(smem + SM_FBB))[sbuf * TP + tid] = bftr[(l + 2) * HID + tid];
            ((float*)(smem + SM_CBB))[((l + 1) & 1) * TP + tid] =
                g_code[l + 1][b][tid] + bfwd[(l + 1) * HID + tid];
            SPLIT_Y(l + 2, sbuf);
        }

        // ---- B: main GEMM (3-term split), acc zero-init (R10 profile) ----
        float acc[2][4][4];
        #pragma unroll
        for (int mt = 0; mt < 2; ++mt)
            #pragma unroll
            for (int nt = 0; nt < 4; ++nt)
                #pragma unroll
                for (int r = 0; r < 4; ++r) acc[mt][nt][r] = 0.f;

        #pragma unroll
        for (int ks = 0; ks < 8; ++ks) {
            const uint32_t k0 = ks * 16;
            uint32_t Ah[2][4], Al[2][4];
            #pragma unroll
            for (int mt = 0; mt < 2; ++mt) {
                uint32_t ro = (uint32_t)(m0w + mt * 16 + (int)aRow) * 272 + (k0 + aK8) * 2;
                ldsm4(Ah[mt], sb + SM_ZH + ro);
                ldsm4(Al[mt], sb + SM_ZL + ro);
            }
            #pragma unroll
            for (int np = 0; np < 2; ++np) {
                uint32_t ro = (uint32_t)(n0w + np * 16 + (int)bRow) * 272 + (k0 + bK8) * 2;
                uint32_t t[4];
                ldsm4(t, sb + SM_WH + ro);
                #pragma unroll
                for (int mt = 0; mt < 2; ++mt) {
                    mma16816(acc[mt][np * 2],     Ah[mt], t);
                    mma16816(acc[mt][np * 2 + 1], Ah[mt], t + 2);
                    mma16816(acc[mt][np * 2],     Al[mt], t);
                    mma16816(acc[mt][np * 2 + 1], Al[mt], t + 2);
                }
                ldsm4(t, sb + SM_WL + ro);
                #pragma unroll
                for (int mt = 0; mt < 2; ++mt) {
                    mma16816(acc[mt][np * 2],     Ah[mt], t);
                    mma16816(acc[mt][np * 2 + 1], Ah[mt], t + 2);
                }
            }
        }

        // ---- C: F[l+2] landed + all Z/W reads done ----
        CP_WAIT(0);
        __syncthreads();

        // ---- D: prefetch W[l+1] ----
        if (l + 1 < DEPTH) {
            const char* ws = (const char*)g_wt[l + 1];
            for (int i = tid; i < 4352; i += NTHR)
                cpa16(sb + SM_WH + i * 16, ws + i * 16);
        }
        CP_COMMIT();

        // ---- E: epilogue combine: z = (acc + cb) * fa  (fb pre-folded) ----
        {
            const float* cbp = (const float*)(smem + SM_CBB) + (l & 1) * TP;
            #pragma unroll
            for (int mt = 0; mt < 2; ++mt)
                #pragma unroll
                for (int nt = 0; nt < 4; ++nt) {
                    int c0 = n0w + nt * 8 + eCol;
                    int r0 = m0w + mt * 16 + eRow;
                    float2 cbv = *(const float2*)&cbp[c0];
                    float z0 = (acc[mt][nt][0] + cbv.x) * fa[mt][nt][0];
                    float z1 = (acc[mt][nt][1] + cbv.y) * fa[mt][nt][1];
                    float z2 = (acc[mt][nt][2] + cbv.x) * fa[mt][nt][2];
                    float z3 = (acc[mt][nt][3] + cbv.y) * fa[mt][nt][3];
                    if (l < DEPTH - 1) {
                        uint32_t hi, lo;
                        uint32_t o0 = (uint32_t)(r0 * 272 + c0 * 2);
                        uint32_t o1 = o0 + 8 * 272;
                        split2(z0, z1, hi, lo);
                        *(uint32_t*)(smem + SM_ZH + o0) = hi;
                        *(uint32_t*)(smem + SM_ZL + o0) = lo;
                        split2(z2, z3, hi, lo);
                        *(uint32_t*)(smem + SM_ZH + o1) = hi;
                        *(uint32_t*)(smem + SM_ZL + o1) = lo;
                    } else {
                        float2 wv = *(const float2*)&wos[c0];
                        os[mt * 2 + 0] = fmaf(z0, wv.x, fmaf(z1, wv.y, os[mt * 2 + 0]));
                        os[mt * 2 + 1] = fmaf(z2, wv.x, fmaf(z3, wv.y, os[mt * 2 + 1]));
                    }
                }
        }

        // ---- E2: fa for next layer (shift l+2, buf sbuf), seeded with fb ----
        if (l < DEPTH - 1) {
            uint32_t Yh[2][4], Yl[2][4];
            uint32_t yb = sb + SM_YB + sbuf * YBSTRIDE;
            uint32_t ft = sb + SM_FT + sbuf * YBSTRIDE;
            const float* fbp2 = (const float*)(smem + SM_FBB) + sbuf * TP;
            #pragma unroll
            for (int mt = 0; mt < 2; ++mt) {
                uint32_t ro = (uint32_t)(m0w + mt * 16 + (int)aRow) * 48 + aK8 * 2;
                ldsm4(Yh[mt], yb + ro);
                ldsm4(Yl[mt], yb + HALFOFF + ro);
            }
            #pragma unroll
            for (int nt = 0; nt < 4; ++nt) {
                uint32_t fo = (uint32_t)(n0w + nt * 8 + (int)fRow) * 48 + fK8 * 2;
                uint32_t Fh[2], Fl[2];
                ldsm2(Fh, ft + fo);
                ldsm2(Fl, ft + HALFOFF + fo);
                float2 fbv = *(const float2*)&fbp2[n0w + nt * 8 + eCol];
                #pragma unroll
                for (int mt = 0; mt < 2; ++mt) {
                    fa[mt][nt][0] = fbv.x; fa[mt][nt][1] = fbv.y;
                    fa[mt][nt][2] = fbv.x; fa[mt][nt][3] = fbv.y;
                    mma16816(fa[mt][nt], Yh[mt], Fh);
                    mma16816(fa[mt][nt], Yh[mt], Fl);
                    mma16816(fa[mt][nt], Yl[mt], Fh);
                }
            }
        }

        // ---- G: W[l+1] landed; publish Z/buffers ----
        CP_WAIT(0);
        __syncthreads();
    }

    // ---- output reduce: 4 warpG partials ----
    {
        #pragma unroll
        for (int i = 0; i < 4; ++i) {
            os[i] += __shfl_xor_sync(0xffffffffu, os[i], 1);
            os[i] += __shfl_xor_sync(0xffffffffu, os[i], 2);
        }
        float* outp = (float*)(smem + SM_OUTP);
        if ((lane & 3) == 0) {
            #pragma unroll
            for (int mt = 0; mt < 2; ++mt) {
                outp[warpG * TP + m0w + mt * 16 + eRow]     = os[mt * 2 + 0];
                outp[warpG * TP + m0w + mt * 16 + 8 + eRow] = os[mt * 2 + 1];
            }
        }
        __syncthreads();
        if (tid < TP)
            out[pt0 + tid] = outp[tid] + outp[TP + tid] + outp[2 * TP + tid] +
                             outp[3 * TP + tid] + *bout;
    }
}

// ---------------------------------------------------------------------------
extern "C" void kernel_launch(void* const* d_in, const int* in_sizes, int n_in,
                              void* d_out, int out_size) {
    const float* x     = (const float*)d_in[0];
    const float* a     = (const float*)d_in[1];
    const float* Wftr  = (const float*)d_in[2];
    const float* bftr  = (const float*)d_in[3];
    const float* Wfwd  = (const float*)d_in[4];
    const float* bfwd  = (const float*)d_in[5];
    const float* Wcode = (const float*)d_in[6];
    const float* bcode = (const float*)d_in[7];
    const float* Wout  = (const float*)d_in[8];
    const float* bout  = (const float*)d_in[9];
    float* out = (float*)d_out;

    prep_all<<<NCODE_BLK + NW_BLK, 256>>>(a, Wcode, bcode, Wfwd, Wftr);

    cudaFuncSetAttribute(sinr_mma, cudaFuncAttributeMaxDynamicSharedMemorySize,
                         SM_TOTAL);
    sinr_mma<<<TOTAL_PTS / TP, NTHR, SM_TOTAL>>>(x, bftr, bfwd, Wout, bout, out);

    if (out_size >= TOTAL_PTS + in_sizes[0]) {
        cudaMemcpyAsync(out + TOTAL_PTS, x, (size_t)in_sizes[0] * sizeof(float),
                        cudaMemcpyDeviceToDevice);
    }
}

// round 13
// speedup vs baseline: 1.3832x; 1.3398x over previous
#include <cuda_runtime.h>
#include <cuda_fp16.h>
#include <math.h>
#include <stdint.h>

#ifndef M_PI
#define M_PI 3.14159265358979323846
#endif

#define DEPTH 5
#define HID 128
#define CODE_D 400
#define NFREQ 9
#define NB 8
#define NPTS 32768
#define TP 128
#define TOTAL_PTS (NB * NPTS)
#define NTHR 512

#define PZ 136   // fp16 pitch for 128-col tiles (Z, W)  -> 272 B/row
#define PY 24    // fp16 pitch for 16-col tiles (Y, F)   -> 48 B/row

// ---------------------------------------------------------------------------
// Device scratch
// ---------------------------------------------------------------------------
__device__ float g_code[DEPTH][NB][HID];
__device__ float g_norm[5][6];
__device__ __align__(16) __half g_wt[DEPTH][2][HID * PZ];      // fp16 hi/lo
__device__ __align__(16) __half g_ft[DEPTH + 1][2][HID * PY];  // fp16 hi/lo

// ---------------------------------------------------------------------------
// SMEM byte map (173,568 B)
// ---------------------------------------------------------------------------
#define SM_CBB   0            // 2 x 128 f32 ping-pong (code+bfwd)
#define SM_FBB   1024         // 2 x 128 f32 ping-pong (bftr)
#define SM_WOUT  2048
#define SM_OUTP  2560         // float[4][128]
#define SM_YS    4608         // 6*128*9 f32 = 27648
#define SM_ZH    32256        // 128*272 = 34816 (single fp16 tile)
#define SM_WH    67072        // 34816
#define SM_WL    101888       // 34816
#define SM_YB    136704       // 2 bufs x 6144 (single fp16 tile each)
#define SM_FT    148992       // 2 bufs x (H 6144 | L 6144) = 24576
#define SM_TOTAL 173568

#define YBUF   6144
#define FBUF   12288
#define FHALF  6144

// ---------------------------------------------------------------------------
// PTX helpers
// ---------------------------------------------------------------------------
__device__ __forceinline__ uint32_t smem_u32(const void* p) {
    uint32_t a;
    asm("{ .reg .u64 t; cvta.to.shared.u64 t, %1; cvt.u32.u64 %0, t; }"
        : "=r"(a) : "l"(p));
    return a;
}
__device__ __forceinline__ void ldsm4(uint32_t* r, uint32_t addr) {
    asm volatile("ldmatrix.sync.aligned.m8n8.x4.shared.b16 {%0,%1,%2,%3}, [%4];"
                 : "=r"(r[0]), "=r"(r[1]), "=r"(r[2]), "=r"(r[3]) : "r"(addr));
}
__device__ __forceinline__ void ldsm2(uint32_t* r, uint32_t addr) {
    asm volatile("ldmatrix.sync.aligned.m8n8.x2.shared.b16 {%0,%1}, [%2];"
                 : "=r"(r[0]), "=r"(r[1]) : "r"(addr));
}
__device__ __forceinline__ void mma16816(float* d, const uint32_t* a, const uint32_t* b) {
    asm volatile(
        "mma.sync.aligned.m16n8k16.row.col.f32.f16.f16.f32 "
        "{%0,%1,%2,%3}, {%4,%5,%6,%7}, {%8,%9}, {%0,%1,%2,%3};"
        : "+f"(d[0]), "+f"(d[1]), "+f"(d[2]), "+f"(d[3])
        : "r"(a[0]), "r"(a[1]), "r"(a[2]), "r"(a[3]), "r"(b[0]), "r"(b[1]));
}
__device__ __forceinline__ uint32_t packh2(float z0, float z1) {
    uint32_t h;
    asm("cvt.rn.f16x2.f32 %0, %1, %2;" : "=r"(h) : "f"(z1), "f"(z0));
    return h;
}
__device__ __forceinline__ void cpa16(uint32_t dst, const void* src) {
    asm volatile("cp.async.cg.shared.global [%0], [%1], 16;" :: "r"(dst), "l"(src));
}
#define CP_COMMIT() asm volatile("cp.async.commit_group;" ::: "memory")
#define CP_WAIT(n)  asm volatile("cp.async.wait_group %0;" :: "n"(n) : "memory")

// ---------------------------------------------------------------------------
// Merged prep kernel
// ---------------------------------------------------------------------------
#define NCODE_BLK (DEPTH * NB * HID / 8)
#define WT_ELEMS (DEPTH * HID * PZ)
#define FT_ELEMS ((DEPTH + 1) * HID * PY)
#define NW_BLK ((WT_ELEMS + FT_ELEMS + 255) / 256)

__global__ void prep_all(const float* __restrict__ a,
                         const float* __restrict__ Wcode,
                         const float* __restrict__ bcode,
                         const float* __restrict__ Wfwd,
                         const float* __restrict__ Wftr) {
    int blk = blockIdx.x, tid = threadIdx.x;
    if (blk < NCODE_BLK) {
        int wid = tid >> 5, lane = tid & 31;
        int gw = blk * 8 + wid;
        int layer = gw >> 10;
        int rem = gw & 1023;
        int b = rem >> 7, h = rem & 127;
        const float* wc = Wcode + (size_t)(layer * HID + h) * CODE_D;
        const float* av = a + b * CODE_D;
        float s = 0.f;
        for (int c = lane; c < CODE_D; c += 32) s = fmaf(av[c], wc[c], s);
        #pragma unroll
        for (int o = 16; o > 0; o >>= 1) s += __shfl_xor_sync(0xffffffffu, s, o);
        if (lane == 0) g_code[layer][b][h] = s + bcode[layer * HID + h];
        if (blk == 0 && wid == 0 && lane < 30) {
            int am = lane / 6, sh = lane % 6, l = am + sh;
            double r = 1.0;
            for (int k = l - am + 1; k <= l + am; ++k) r /= (double)k;
            g_norm[am][sh] = (float)sqrt((2.0 * l + 1.0) / (4.0 * M_PI) * r);
        }
    } else {
        int i = (blk - NCODE_BLK) * 256 + tid;
        if (i < WT_ELEMS) {
            int l = i / (HID * PZ), r = i % (HID * PZ), g = r / PZ, c = r % PZ;
            float v = (c < HID) ? Wfwd[(l * HID + g) * HID + c] : 0.f;
            __half hi = __float2half(v);
            __half lo = __float2half(v - __half2float(hi));
            g_wt[l][0][r] = hi;
            g_wt[l][1][r] = lo;
        } else if (i < WT_ELEMS + FT_ELEMS) {
            int j = i - WT_ELEMS;
            int s = j / (HID * PY), r = j % (HID * PY), h = r / PY, f = r % PY;
            float v = (f < NFREQ) ? Wftr[(s * HID + h) * NFREQ + f] : 0.f;
            __half hi = __float2half(v);
            __half lo = __float2half(v - __half2float(hi));
            g_ft[s][0][r] = hi;
            g_ft[s][1][r] = lo;
        }
    }
}

// ---------------------------------------------------------------------------
// Main kernel: 512 threads, 4x4 warp grid (warp tile 32m x 32n), fp16 2-term
// ---------------------------------------------------------------------------
__global__ __launch_bounds__(NTHR, 1)
void sinr_mma(const float* __restrict__ x,
              const float* __restrict__ bftr,
              const float* __restrict__ bfwd,
              const float* __restrict__ Wout,
              const float* __restrict__ bout,
              float* __restrict__ out) {
    extern __shared__ char smem[];
    const uint32_t sb = smem_u32(smem);
    const int tid = threadIdx.x, wid = tid >> 5, lane = tid & 31;
    const int blk = blockIdx.x, pt0 = blk * TP, b = blk >> 8;

    const int warpP = wid & 3, warpG = wid >> 2;
    const int m0w = warpP * 32, n0w = warpG * 32;

    // ---- prologue cp.async: F0->buf0 (g1), W0 (g2), F1->buf1 (g3) ----
    {
        const char* f0 = (const char*)g_ft[0];
        for (int i = tid; i < 768; i += NTHR)
            cpa16(sb + SM_FT + i * 16, f0 + i * 16);
        CP_COMMIT();
        const char* ws = (const char*)g_wt[0];
        for (int i = tid; i < 4352; i += NTHR)
            cpa16(sb + SM_WH + i * 16, ws + i * 16);
        CP_COMMIT();
        const char* f1 = (const char*)g_ft[1];
        for (int i = tid; i < 768; i += NTHR)
            cpa16(sb + SM_FT + FBUF + i * 16, f1 + i * 16);
        CP_COMMIT();
    }

    // ---- spherical harmonics into Ys (fp32), one point per thread ----
    if (tid < TP) {
        float theta = x[(pt0 + tid) * 2 + 0];
        float phi   = x[(pt0 + tid) * 2 + 1];
        float c = cosf(phi);
        float s2 = sqrtf(fmaxf(1.f - c * c, 0.f));
        float P[5][6];
        float pmm = 1.f;
        #pragma unroll
        for (int am = 0; am < 5; ++am) {
            if (am > 0) pmm *= -(2.f * am - 1.f) * s2;
            float p0 = pmm;
            P[am][0] = p0;
            float p1 = c * (2.f * am + 1.f) * pmm;
            P[am][1] = p1;
            #pragma unroll
            for (int sh = 2; sh < 6; ++sh) {
                int l = am + sh;
                float pl = ((2.f * l - 1.f) * c * p1 - (l + am - 1.f) * p0) * (1.f / (float)sh);
                p0 = p1; p1 = pl;
                P[am][sh] = pl;
            }
        }
        float ck[5], sk[5], c1, s1;
        sincosf(theta, &s1, &c1);
        ck[0] = 1.f; sk[0] = 0.f;
        ck[1] = c1;  sk[1] = s1;
        #pragma unroll
        for (int m = 2; m < 5; ++m) {
            ck[m] = c1 * ck[m - 1] - s1 * sk[m - 1];
            sk[m] = s1 * ck[m - 1] + c1 * sk[m - 1];
        }
        const float SQ2 = 1.41421356237309515f;
        float* Ys = (float*)(smem + SM_YS);
        #pragma unroll
        for (int s = 0; s < 6; ++s) {
            float* yrow = &Ys[(s * TP + tid) * NFREQ];
            yrow[4] = g_norm[0][s] * P[0][s];
            #pragma unroll
            for (int am = 1; am < 5; ++am) {
                float base = SQ2 * g_norm[am][s] * P[am][s];
                if (am & 1) base = -base;
                yrow[4 + am] = base * ck[am];
                yrow[4 - am] = base * sk[am];
            }
        }
    }

    // ---- Y convert macro: shift s -> YB buffer buf (single fp16) ----
    #define SPLIT_Y(s, buf)                                                      \
        {                                                                        \
            const float* yr = (const float*)(smem + SM_YS) + ((s) * TP + tid) * NFREQ; \
            __half* yh = (__half*)(smem + SM_YB + (buf) * YBUF) + tid * PY;      \
            _Pragma("unroll")                                                    \
            for (int f = 0; f < NFREQ; ++f) yh[f] = __float2half(yr[f]);         \
        }

    // ---- init staging: biases, wout, zero Y pads, Y0/Y1 converts ----
    if (tid < TP) {
        ((float*)(smem + SM_FBB))[tid] = bftr[tid];
        ((float*)(smem + SM_FBB))[TP + tid] = bftr[HID + tid];
        ((float*)(smem + SM_CBB))[tid] = g_code[0][b][tid] + bfwd[tid];
        ((float*)(smem + SM_WOUT))[tid] = Wout[tid];
        #pragma unroll
        for (int bu = 0; bu < 2; ++bu) {
            __half* yh = (__half*)(smem + SM_YB + bu * YBUF) + tid * PY;
            #pragma unroll
            for (int f = NFREQ; f < 16; ++f) yh[f] = __float2half(0.f);
        }
        SPLIT_Y(0, 0);
        SPLIT_Y(1, 1);
    }
    CP_WAIT(0);      // F0, W0, F1 all landed
    __syncthreads();

    // lane address components
    const uint32_t aRow = (uint32_t)(lane & 15);
    const uint32_t aK8  = (uint32_t)((lane >> 4) * 8);
    const uint32_t bRow = (uint32_t)((lane & 7) + ((lane >> 4) & 1) * 8);
    const uint32_t bK8  = (uint32_t)(((lane >> 3) & 1) * 8);
    const uint32_t fRow = (uint32_t)(lane & 7);
    const uint32_t fK8  = (uint32_t)(((lane >> 3) & 1) * 8);

    const float* wos = (const float*)(smem + SM_WOUT);
    const int eRow = lane >> 2;
    const int eCol = (lane & 3) * 2;

    float fa[2][4][4];     // feature MMA results (seeded with fb) for the epilogue
    float os[4] = {0.f, 0.f, 0.f, 0.f};

    // ---- init: z0 = fb0 + Y0*F0^T -> Z;  then fa (seeded fb1) for layer 0 ----
    {
        const float* fb = (const float*)(smem + SM_FBB);   // buf0
        uint32_t Yh[2][4];
        #pragma unroll
        for (int mt = 0; mt < 2; ++mt) {
            uint32_t ro = (uint32_t)(m0w + mt * 16 + (int)aRow) * 48 + aK8 * 2;
            ldsm4(Yh[mt], sb + SM_YB + ro);
        }
        #pragma unroll
        for (int nt = 0; nt < 4; ++nt) {
            uint32_t fo = (uint32_t)(n0w + nt * 8 + (int)fRow) * 48 + fK8 * 2;
            uint32_t Fh[2], Fl[2];
            ldsm2(Fh, sb + SM_FT + fo);
            ldsm2(Fl, sb + SM_FT + FHALF + fo);
            int c0 = n0w + nt * 8 + eCol;
            float2 fbv = *(const float2*)&fb[c0];
            #pragma unroll
            for (int mt = 0; mt < 2; ++mt) {
                float t4[4] = {fbv.x, fbv.y, fbv.x, fbv.y};
                mma16816(t4, Yh[mt], Fh);
                mma16816(t4, Yh[mt], Fl);
                int r0 = m0w + mt * 16 + eRow;
                uint32_t o0 = (uint32_t)(r0 * 272 + c0 * 2);
                uint32_t o1 = o0 + 8 * 272;
                *(uint32_t*)(smem + SM_ZH + o0) = packh2(t4[0], t4[1]);
                *(uint32_t*)(smem + SM_ZH + o1) = packh2(t4[2], t4[3]);
            }
        }
        // fa for layer 0 = shift 1 tiles (buf 1), seeded with fb1
        const float* fb1 = (const float*)(smem + SM_FBB) + TP;
        #pragma unroll
        for (int mt = 0; mt < 2; ++mt) {
            uint32_t ro = (uint32_t)(m0w + mt * 16 + (int)aRow) * 48 + aK8 * 2;
            ldsm4(Yh[mt], sb + SM_YB + YBUF + ro);
        }
        #pragma unroll
        for (int nt = 0; nt < 4; ++nt) {
            uint32_t fo = (uint32_t)(n0w + nt * 8 + (int)fRow) * 48 + fK8 * 2;
            uint32_t Fh[2], Fl[2];
            ldsm2(Fh, sb + SM_FT + FBUF + fo);
            ldsm2(Fl, sb + SM_FT + FBUF + FHALF + fo);
            int c0 = n0w + nt * 8 + eCol;
            float2 fbv = *(const float2*)&fb1[c0];
            #pragma unroll
            for (int mt = 0; mt < 2; ++mt) {
                fa[mt][nt][0] = fbv.x; fa[mt][nt][1] = fbv.y;
                fa[mt][nt][2] = fbv.x; fa[mt][nt][3] = fbv.y;
                mma16816(fa[mt][nt], Yh[mt], Fh);
                mma16816(fa[mt][nt], Yh[mt], Fl);
            }
        }
    }
    __syncthreads();

    // =========================== 5 fused layers =============================
    #pragma unroll 1
    for (int l = 0; l < DEPTH; ++l) {
        const int sbuf = l & 1;   // buffer for shift l+2 (staged now, fa'd at E2)

        // ---- A: stage shift l+2 F tiles + biases + Y convert (no barrier) ----
        if (l <= 3) {
            const char* fs = (const char*)g_ft[l + 2];
            for (int i = tid; i < 768; i += NTHR)
                cpa16(sb + SM_FT + sbuf * FBUF + i * 16, fs + i * 16);
        }
        CP_COMMIT();
        if (tid < TP && l <= 3) {
            ((float*)(smem + SM_FBB))[sbuf * TP + tid] = bftr[(l + 2) * HID + tid];
            ((float*)(smem + SM_CBB))[((l + 1) & 1) * TP + tid] =
                g_code[l + 1][b][tid] + bfwd[(l + 1) * HID + tid];
            SPLIT_Y(l + 2, sbuf);
        }

        // ---- B: main GEMM (2-term fp16: zh*wh + zh*wl) ----
        float acc[2][4][4];
        #pragma unroll
        for (int mt = 0; mt < 2; ++mt)
            #pragma unroll
            for (int nt = 0; nt < 4; ++nt)
                #pragma unroll
                for (int r = 0; r < 4; ++r) acc[mt][nt][r] = 0.f;

        #pragma unroll
        for (int ks = 0; ks < 8; ++ks) {
            const uint32_t k0 = ks * 16;
            uint32_t Ah[2][4];
            #pragma unroll
            for (int mt = 0; mt < 2; ++mt) {
                uint32_t ro = (uint32_t)(m0w + mt * 16 + (int)aRow) * 272 + (k0 + aK8) * 2;
                ldsm4(Ah[mt], sb + SM_ZH + ro);
            }
            #pragma unroll
            for (int np = 0; np < 2; ++np) {
                uint32_t ro = (uint32_t)(n0w + np * 16 + (int)bRow) * 272 + (k0 + bK8) * 2;
                uint32_t t[4];
                ldsm4(t, sb + SM_WH + ro);
                #pragma unroll
                for (int mt = 0; mt < 2; ++mt) {
                    mma16816(acc[mt][np * 2],     Ah[mt], t);
                    mma16816(acc[mt][np * 2 + 1], Ah[mt], t + 2);
                }
                ldsm4(t, sb + SM_WL + ro);
                #pragma unroll
                for (int mt = 0; mt < 2; ++mt) {
                    mma16816(acc[mt][np * 2],     Ah[mt], t);
                    mma16816(acc[mt][np * 2 + 1], Ah[mt], t + 2);
                }
            }
        }

        // ---- C: F[l+2] landed + all Z/W reads done ----
        CP_WAIT(0);
        __syncthreads();

        // ---- D: prefetch W[l+1] ----
        if (l + 1 < DEPTH) {
            const char* ws = (const char*)g_wt[l + 1];
            for (int i = tid; i < 4352; i += NTHR)
                cpa16(sb + SM_WH + i * 16, ws + i * 16);
        }
        CP_COMMIT();

        // ---- E: epilogue combine: z = (acc + cb) * fa  (fb pre-folded) ----
        {
            const float* cbp = (const float*)(smem + SM_CBB) + (l & 1) * TP;
            #pragma unroll
            for (int mt = 0; mt < 2; ++mt)
                #pragma unroll
                for (int nt = 0; nt < 4; ++nt) {
                    int c0 = n0w + nt * 8 + eCol;
                    int r0 = m0w + mt * 16 + eRow;
                    float2 cbv = *(const float2*)&cbp[c0];
                    float z0 = (acc[mt][nt][0] + cbv.x) * fa[mt][nt][0];
                    float z1 = (acc[mt][nt][1] + cbv.y) * fa[mt][nt][1];
                    float z2 = (acc[mt][nt][2] + cbv.x) * fa[mt][nt][2];
                    float z3 = (acc[mt][nt][3] + cbv.y) * fa[mt][nt][3];
                    if (l < DEPTH - 1) {
                        uint32_t o0 = (uint32_t)(r0 * 272 + c0 * 2);
                        uint32_t o1 = o0 + 8 * 272;
                        *(uint32_t*)(smem + SM_ZH + o0) = packh2(z0, z1);
                        *(uint32_t*)(smem + SM_ZH + o1) = packh2(z2, z3);
                    } else {
                        float2 wv = *(const float2*)&wos[c0];
                        os[mt * 2 + 0] = fmaf(z0, wv.x, fmaf(z1, wv.y, os[mt * 2 + 0]));
                        os[mt * 2 + 1] = fmaf(z2, wv.x, fmaf(z3, wv.y, os[mt * 2 + 1]));
                    }
                }
        }

        // ---- E2: fa for next layer (shift l+2, buf sbuf), seeded with fb ----
        if (l < DEPTH - 1) {
            uint32_t Yh[2][4];
            uint32_t yb = sb + SM_YB + sbuf * YBUF;
            uint32_t ft = sb + SM_FT + sbuf * FBUF;
            const float* fbp2 = (const float*)(smem + SM_FBB) + sbuf * TP;
            #pragma unroll
            for (int mt = 0; mt < 2; ++mt) {
                uint32_t ro = (uint32_t)(m0w + mt * 16 + (int)aRow) * 48 + aK8 * 2;
                ldsm4(Yh[mt], yb + ro);
            }
            #pragma unroll
            for (int nt = 0; nt < 4; ++nt) {
                uint32_t fo = (uint32_t)(n0w + nt * 8 + (int)fRow) * 48 + fK8 * 2;
                uint32_t Fh[2], Fl[2];
                ldsm2(Fh, ft + fo);
                ldsm2(Fl, ft + FHALF + fo);
                float2 fbv = *(const float2*)&fbp2[n0w + nt * 8 + eCol];
                #pragma unroll
                for (int mt = 0; mt < 2; ++mt) {
                    fa[mt][nt][0] = fbv.x; fa[mt][nt][1] = fbv.y;
                    fa[mt][nt][2] = fbv.x; fa[mt][nt][3] = fbv.y;
                    mma16816(fa[mt][nt], Yh[mt], Fh);
                    mma16816(fa[mt][nt], Yh[mt], Fl);
                }
            }
        }

        // ---- G: W[l+1] landed; publish Z/buffers ----
        CP_WAIT(0);
        __syncthreads();
    }

    // ---- output reduce: 4 warpG partials ----
    {
        #pragma unroll
        for (int i = 0; i < 4; ++i) {
            os[i] += __shfl_xor_sync(0xffffffffu, os[i], 1);
            os[i] += __shfl_xor_sync(0xffffffffu, os[i], 2);
        }
        float* outp = (float*)(smem + SM_OUTP);
        if ((lane & 3) == 0) {
            #pragma unroll
            for (int mt = 0; mt < 2; ++mt) {
                outp[warpG * TP + m0w + mt * 16 + eRow]     = os[mt * 2 + 0];
                outp[warpG * TP + m0w + mt * 16 + 8 + eRow] = os[mt * 2 + 1];
            }
        }
        __syncthreads();
        if (tid < TP)
            out[pt0 + tid] = outp[tid] + outp[TP + tid] + outp[2 * TP + tid] +
                             outp[3 * TP + tid] + *bout;
    }
}

// ---------------------------------------------------------------------------
extern "C" void kernel_launch(void* const* d_in, const int* in_sizes, int n_in,
                              void* d_out, int out_size) {
    const float* x     = (const float*)d_in[0];
    const float* a     = (const float*)d_in[1];
    const float* Wftr  = (const float*)d_in[2];
    const float* bftr  = (const float*)d_in[3];
    const float* Wfwd  = (const float*)d_in[4];
    const float* bfwd  = (const float*)d_in[5];
    const float* Wcode = (const float*)d_in[6];
    const float* bcode = (const float*)d_in[7];
    const float* Wout  = (const float*)d_in[8];
    const float* bout  = (const float*)d_in[9];
    float* out = (float*)d_out;

    prep_all<<<NCODE_BLK + NW_BLK, 256>>>(a, Wcode, bcode, Wfwd, Wftr);

    cudaFuncSetAttribute(sinr_mma, cudaFuncAttributeMaxDynamicSharedMemorySize,
                         SM_TOTAL);
    sinr_mma<<<TOTAL_PTS / TP, NTHR, SM_TOTAL>>>(x, bftr, bfwd, Wout, bout, out);

    if (out_size >= TOTAL_PTS + in_sizes[0]) {
        cudaMemcpyAsync(out + TOTAL_PTS, x, (size_t)in_sizes[0] * sizeof(float),
                        cudaMemcpyDeviceToDevice);
    }
}

// round 15
// speedup vs baseline: 2.0715x; 1.4976x over previous
#include <cuda_runtime.h>
#include <cuda_fp16.h>
#include <math.h>
#include <stdint.h>

#ifndef M_PI
#define M_PI 3.14159265358979323846
#endif

#define DEPTH 5
#define HID 128
#define CODE_D 400
#define NFREQ 9
#define NB 8
#define NPTS 32768
#define TP 128
#define TOTAL_PTS (NB * NPTS)
#define NTHR 512

#define PZ 136   // fp16 pitch for 128-col tiles (Z, W)  -> 272 B/row
#define PY 24    // fp16 pitch for 16-col tiles (Y, F)   -> 48 B/row

// ---------------------------------------------------------------------------
// Device scratch
// ---------------------------------------------------------------------------
__device__ float g_code[DEPTH][NB][HID];
__device__ float g_norm[5][6];
__device__ __align__(16) __half g_wt[DEPTH][HID * PZ];      // single fp16
__device__ __align__(16) __half g_ft[DEPTH + 1][HID * PY];  // single fp16

// ---------------------------------------------------------------------------
// SMEM byte map (126,464 B)
// ---------------------------------------------------------------------------
#define SM_CBB   0            // 2 x 128 f32 ping-pong (code+bfwd)
#define SM_FBB   1024         // 2 x 128 f32 ping-pong (bftr)
#define SM_WOUT  2048
#define SM_OUTP  2560         // float[4][128]
#define SM_YS    4608         // 6*128*9 f32 = 27648
#define SM_ZH    32256        // 128*272 = 34816
#define SM_WH    67072        // 34816
#define SM_YB    101888       // 2 bufs x 6144
#define SM_FT    114176       // 2 bufs x 6144
#define SM_TOTAL 126464

#define YBUF   6144
#define FBUF   6144

// ---------------------------------------------------------------------------
// PTX helpers
// ---------------------------------------------------------------------------
__device__ __forceinline__ uint32_t smem_u32(const void* p) {
    uint32_t a;
    asm("{ .reg .u64 t; cvta.to.shared.u64 t, %1; cvt.u32.u64 %0, t; }"
        : "=r"(a) : "l"(p));
    return a;
}
__device__ __forceinline__ void ldsm4(uint32_t* r, uint32_t addr) {
    asm volatile("ldmatrix.sync.aligned.m8n8.x4.shared.b16 {%0,%1,%2,%3}, [%4];"
                 : "=r"(r[0]), "=r"(r[1]), "=r"(r[2]), "=r"(r[3]) : "r"(addr));
}
__device__ __forceinline__ void ldsm2(uint32_t* r, uint32_t addr) {
    asm volatile("ldmatrix.sync.aligned.m8n8.x2.shared.b16 {%0,%1}, [%2];"
                 : "=r"(r[0]), "=r"(r[1]) : "r"(addr));
}
__device__ __forceinline__ void mma16816(float* d, const uint32_t* a, const uint32_t* b) {
    asm volatile(
        "mma.sync.aligned.m16n8k16.row.col.f32.f16.f16.f32 "
        "{%0,%1,%2,%3}, {%4,%5,%6,%7}, {%8,%9}, {%0,%1,%2,%3};"
        : "+f"(d[0]), "+f"(d[1]), "+f"(d[2]), "+f"(d[3])
        : "r"(a[0]), "r"(a[1]), "r"(a[2]), "r"(a[3]), "r"(b[0]), "r"(b[1]));
}
__device__ __forceinline__ uint32_t packh2(float z0, float z1) {
    uint32_t h;
    asm("cvt.rn.f16x2.f32 %0, %1, %2;" : "=r"(h) : "f"(z1), "f"(z0));
    return h;
}
__device__ __forceinline__ void cpa16(uint32_t dst, const void* src) {
    asm volatile("cp.async.cg.shared.global [%0], [%1], 16;" :: "r"(dst), "l"(src));
}
#define CP_COMMIT() asm volatile("cp.async.commit_group;" ::: "memory")
#define CP_WAIT(n)  asm volatile("cp.async.wait_group %0;" :: "n"(n) : "memory")

// ---------------------------------------------------------------------------
// Merged prep kernel
// ---------------------------------------------------------------------------
#define NCODE_BLK (DEPTH * NB * HID / 8)
#define WT_ELEMS (DEPTH * HID * PZ)
#define FT_ELEMS ((DEPTH + 1) * HID * PY)
#define NW_BLK ((WT_ELEMS + FT_ELEMS + 255) / 256)

__global__ void prep_all(const float* __restrict__ a,
                         const float* __restrict__ Wcode,
                         const float* __restrict__ bcode,
                         const float* __restrict__ Wfwd,
                         const float* __restrict__ Wftr) {
    int blk = blockIdx.x, tid = threadIdx.x;
    if (blk < NCODE_BLK) {
        int wid = tid >> 5, lane = tid & 31;
        int gw = blk * 8 + wid;
        int layer = gw >> 10;
        int rem = gw & 1023;
        int b = rem >> 7, h = rem & 127;
        const float* wc = Wcode + (size_t)(layer * HID + h) * CODE_D;
        const float* av = a + b * CODE_D;
        float s = 0.f;
        for (int c = lane; c < CODE_D; c += 32) s = fmaf(av[c], wc[c], s);
        #pragma unroll
        for (int o = 16; o > 0; o >>= 1) s += __shfl_xor_sync(0xffffffffu, s, o);
        if (lane == 0) g_code[layer][b][h] = s + bcode[layer * HID + h];
        if (blk == 0 && wid == 0 && lane < 30) {
            int am = lane / 6, sh = lane % 6, l = am + sh;
            double r = 1.0;
            for (int k = l - am + 1; k <= l + am; ++k) r /= (double)k;
            g_norm[am][sh] = (float)sqrt((2.0 * l + 1.0) / (4.0 * M_PI) * r);
        }
    } else {
        int i = (blk - NCODE_BLK) * 256 + tid;
        if (i < WT_ELEMS) {
            int l = i / (HID * PZ), r = i % (HID * PZ), g = r / PZ, c = r % PZ;
            float v = (c < HID) ? Wfwd[(l * HID + g) * HID + c] : 0.f;
            g_wt[l][r] = __float2half(v);
        } else if (i < WT_ELEMS + FT_ELEMS) {
            int j = i - WT_ELEMS;
            int s = j / (HID * PY), r = j % (HID * PY), h = r / PY, f = r % PY;
            float v = (f < NFREQ) ? Wftr[(s * HID + h) * NFREQ + f] : 0.f;
            g_ft[s][r] = __float2half(v);
        }
    }
}

// ---------------------------------------------------------------------------
// Main kernel: 512 threads, 4x4 warp grid (warp tile 32m x 32n), pure fp16
// ---------------------------------------------------------------------------
__global__ __launch_bounds__(NTHR, 1)
void sinr_mma(const float* __restrict__ x,
              const float* __restrict__ bftr,
              const float* __restrict__ bfwd,
              const float* __restrict__ Wout,
              const float* __restrict__ bout,
              float* __restrict__ out) {
    extern __shared__ char smem[];
    const uint32_t sb = smem_u32(smem);
    const int tid = threadIdx.x, wid = tid >> 5, lane = tid & 31;
    const int blk = blockIdx.x, pt0 = blk * TP, b = blk >> 8;

    const int warpP = wid & 3, warpG = wid >> 2;
    const int m0w = warpP * 32, n0w = warpG * 32;

    // ---- prologue cp.async: F0->buf0 (g1), W0 (g2), F1->buf1 (g3) ----
    {
        const char* f0 = (const char*)g_ft[0];
        for (int i = tid; i < 384; i += NTHR)
            cpa16(sb + SM_FT + i * 16, f0 + i * 16);
        CP_COMMIT();
        const char* ws = (const char*)g_wt[0];
        for (int i = tid; i < 2176; i += NTHR)
            cpa16(sb + SM_WH + i * 16, ws + i * 16);
        CP_COMMIT();
        const char* f1 = (const char*)g_ft[1];
        for (int i = tid; i < 384; i += NTHR)
            cpa16(sb + SM_FT + FBUF + i * 16, f1 + i * 16);
        CP_COMMIT();
    }

    // ---- spherical harmonics into Ys (fp32), one point per thread ----
    if (tid < TP) {
        float theta = x[(pt0 + tid) * 2 + 0];
        float phi   = x[(pt0 + tid) * 2 + 1];
        float c = cosf(phi);
        float s2 = sqrtf(fmaxf(1.f - c * c, 0.f));
        float P[5][6];
        float pmm = 1.f;
        #pragma unroll
        for (int am = 0; am < 5; ++am) {
            if (am > 0) pmm *= -(2.f * am - 1.f) * s2;
            float p0 = pmm;
            P[am][0] = p0;
            float p1 = c * (2.f * am + 1.f) * pmm;
            P[am][1] = p1;
            #pragma unroll
            for (int sh = 2; sh < 6; ++sh) {
                int l = am + sh;
                float pl = ((2.f * l - 1.f) * c * p1 - (l + am - 1.f) * p0) * (1.f / (float)sh);
                p0 = p1; p1 = pl;
                P[am][sh] = pl;
            }
        }
        float ck[5], sk[5], c1, s1;
        sincosf(theta, &s1, &c1);
        ck[0] = 1.f; sk[0] = 0.f;
        ck[1] = c1;  sk[1] = s1;
        #pragma unroll
        for (int m = 2; m < 5; ++m) {
            ck[m] = c1 * ck[m - 1] - s1 * sk[m - 1];
            sk[m] = s1 * ck[m - 1] + c1 * sk[m - 1];
        }
        const float SQ2 = 1.41421356237309515f;
        float* Ys = (float*)(smem + SM_YS);
        #pragma unroll
        for (int s = 0; s < 6; ++s) {
            float* yrow = &Ys[(s * TP + tid) * NFREQ];
            yrow[4] = g_norm[0][s] * P[0][s];
            #pragma unroll
            for (int am = 1; am < 5; ++am) {
                float base = SQ2 * g_norm[am][s] * P[am][s];
                if (am & 1) base = -base;
                yrow[4 + am] = base * ck[am];
                yrow[4 - am] = base * sk[am];
            }
        }
    }

    // ---- Y convert macro: shift s -> YB buffer buf (single fp16) ----
    #define SPLIT_Y(s, buf)                                                      \
        {                                                                        \
            const float* yr = (const float*)(smem + SM_YS) + ((s) * TP + tid) * NFREQ; \
            __half* yh = (__half*)(smem + SM_YB + (buf) * YBUF) + tid * PY;      \
            _Pragma("unroll")                                                    \
            for (int f = 0; f < NFREQ; ++f) yh[f] = __float2half(yr[f]);         \
        }

    // ---- init staging: biases, wout, zero Y pads, Y0/Y1 converts ----
    if (tid < TP) {
        ((float*)(smem + SM_FBB))[tid] = bftr[tid];
        ((float*)(smem + SM_FBB))[TP + tid] = bftr[HID + tid];
        ((float*)(smem + SM_CBB))[tid] = g_code[0][b][tid] + bfwd[tid];
        ((float*)(smem + SM_WOUT))[tid] = Wout[tid];
        #pragma unroll
        for (int bu = 0; bu < 2; ++bu) {
            __half* yh = (__half*)(smem + SM_YB + bu * YBUF) + tid * PY;
            #pragma unroll
            for (int f = NFREQ; f < 16; ++f) yh[f] = __float2half(0.f);
        }
        SPLIT_Y(0, 0);
        SPLIT_Y(1, 1);
    }
    CP_WAIT(0);      // F0, W0, F1 all landed
    __syncthreads();

    // lane address components
    const uint32_t aRow = (uint32_t)(lane & 15);
    const uint32_t aK8  = (uint32_t)((lane >> 4) * 8);
    const uint32_t bRow = (uint32_t)((lane & 7) + ((lane >> 4) & 1) * 8);
    const uint32_t bK8  = (uint32_t)(((lane >> 3) & 1) * 8);
    const uint32_t fRow = (uint32_t)(lane & 7);
    const uint32_t fK8  = (uint32_t)(((lane >> 3) & 1) * 8);

    const float* wos = (const float*)(smem + SM_WOUT);
    const int eRow = lane >> 2;
    const int eCol = (lane & 3) * 2;

    float fa[2][4][4];     // feature MMA results (seeded with fb) for the epilogue
    float os[4] = {0.f, 0.f, 0.f, 0.f};

    // ---- init: z0 = fb0 + Y0*F0^T -> Z;  then fa (seeded fb1) for layer 0 ----
    {
        const float* fb = (const float*)(smem + SM_FBB);   // buf0
        uint32_t Yh[2][4];
        #pragma unroll
        for (int mt = 0; mt < 2; ++mt) {
            uint32_t ro = (uint32_t)(m0w + mt * 16 + (int)aRow) * 48 + aK8 * 2;
            ldsm4(Yh[mt], sb + SM_YB + ro);
        }
        #pragma unroll
        for (int nt = 0; nt < 4; ++nt) {
            uint32_t fo = (uint32_t)(n0w + nt * 8 + (int)fRow) * 48 + fK8 * 2;
            uint32_t Fh[2];
            ldsm2(Fh, sb + SM_FT + fo);
            int c0 = n0w + nt * 8 + eCol;
            float2 fbv = *(const float2*)&fb[c0];
            #pragma unroll
            for (int mt = 0; mt < 2; ++mt) {
                float t4[4] = {fbv.x, fbv.y, fbv.x, fbv.y};
                mma16816(t4, Yh[mt], Fh);
                int r0 = m0w + mt * 16 + eRow;
                uint32_t o0 = (uint32_t)(r0 * 272 + c0 * 2);
                uint32_t o1 = o0 + 8 * 272;
                *(uint32_t*)(smem + SM_ZH + o0) = packh2(t4[0], t4[1]);
                *(uint32_t*)(smem + SM_ZH + o1) = packh2(t4[2], t4[3]);
            }
        }
        // fa for layer 0 = shift 1 tiles (buf 1), seeded with fb1
        const float* fb1 = (const float*)(smem + SM_FBB) + TP;
        #pragma unroll
        for (int mt = 0; mt < 2; ++mt) {
            uint32_t ro = (uint32_t)(m0w + mt * 16 + (int)aRow) * 48 + aK8 * 2;
            ldsm4(Yh[mt], sb + SM_YB + YBUF + ro);
        }
        #pragma unroll
        for (int nt = 0; nt < 4; ++nt) {
            uint32_t fo = (uint32_t)(n0w + nt * 8 + (int)fRow) * 48 + fK8 * 2;
            uint32_t Fh[2];
            ldsm2(Fh, sb + SM_FT + FBUF + fo);
            int c0 = n0w + nt * 8 + eCol;
            float2 fbv = *(const float2*)&fb1[c0];
            #pragma unroll
            for (int mt = 0; mt < 2; ++mt) {
                fa[mt][nt][0] = fbv.x; fa[mt][nt][1] = fbv.y;
                fa[mt][nt][2] = fbv.x; fa[mt][nt][3] = fbv.y;
                mma16816(fa[mt][nt], Yh[mt], Fh);
            }
        }
    }
    __syncthreads();

    // =========================== 5 fused layers =============================
    #pragma unroll 1
    for (int l = 0; l < DEPTH; ++l) {
        const int sbuf = l & 1;   // buffer for shift l+2 (staged now, fa'd at E2)

        // ---- A: stage shift l+2 F tiles + biases + Y convert (no barrier) ----
        if (l <= 3) {
            const char* fs = (const char*)g_ft[l + 2];
            for (int i = tid; i < 384; i += NTHR)
                cpa16(sb + SM_FT + sbuf * FBUF + i * 16, fs + i * 16);
        }
        CP_COMMIT();
        if (tid < TP && l <= 3) {
            ((float*)(smem + SM_FBB))[sbuf * TP + tid] = bftr[(l + 2) * HID + tid];
            ((float*)(smem + SM_CBB))[((l + 1) & 1) * TP + tid] =
                g_code[l + 1][b][tid] + bfwd[(l + 1) * HID + tid];
            SPLIT_Y(l + 2, sbuf);
        }

        // ---- B: main GEMM (pure fp16) ----
        float acc[2][4][4];
        #pragma unroll
        for (int mt = 0; mt < 2; ++mt)
            #pragma unroll
            for (int nt = 0; nt < 4; ++nt)
                #pragma unroll
                for (int r = 0; r < 4; ++r) acc[mt][nt][r] = 0.f;

        #pragma unroll
        for (int ks = 0; ks < 8; ++ks) {
            const uint32_t k0 = ks * 16;
            uint32_t Ah[2][4];
            #pragma unroll
            for (int mt = 0; mt < 2; ++mt) {
                uint32_t ro = (uint32_t)(m0w + mt * 16 + (int)aRow) * 272 + (k0 + aK8) * 2;
                ldsm4(Ah[mt], sb + SM_ZH + ro);
            }
            #pragma unroll
            for (int np = 0; np < 2; ++np) {
                uint32_t ro = (uint32_t)(n0w + np * 16 + (int)bRow) * 272 + (k0 + bK8) * 2;
                uint32_t t[4];
                ldsm4(t, sb + SM_WH + ro);
                #pragma unroll
                for (int mt = 0; mt < 2; ++mt) {
                    mma16816(acc[mt][np * 2],     Ah[mt], t);
                    mma16816(acc[mt][np * 2 + 1], Ah[mt], t + 2);
                }
            }
        }

        // ---- C: F[l+2] landed + all Z/W reads done ----
        CP_WAIT(0);
        __syncthreads();

        // ---- D: prefetch W[l+1] ----
        if (l + 1 < DEPTH) {
            const char* ws = (const char*)g_wt[l + 1];
            for (int i = tid; i < 2176; i += NTHR)
                cpa16(sb + SM_WH + i * 16, ws + i * 16);
        }
        CP_COMMIT();

        // ---- E: epilogue combine: z = (acc + cb) * fa  (fb pre-folded) ----
        {
            const float* cbp = (const float*)(smem + SM_CBB) + (l & 1) * TP;
            #pragma unroll
            for (int mt = 0; mt < 2; ++mt)
                #pragma unroll
                for (int nt = 0; nt < 4; ++nt) {
                    int c0 = n0w + nt * 8 + eCol;
                    int r0 = m0w + mt * 16 + eRow;
                    float2 cbv = *(const float2*)&cbp[c0];
                    float z0 = (acc[mt][nt][0] + cbv.x) * fa[mt][nt][0];
                    float z1 = (acc[mt][nt][1] + cbv.y) * fa[mt][nt][1];
                    float z2 = (acc[mt][nt][2] + cbv.x) * fa[mt][nt][2];
                    float z3 = (acc[mt][nt][3] + cbv.y) * fa[mt][nt][3];
                    if (l < DEPTH - 1) {
                        uint32_t o0 = (uint32_t)(r0 * 272 + c0 * 2);
                        uint32_t o1 = o0 + 8 * 272;
                        *(uint32_t*)(smem + SM_ZH + o0) = packh2(z0, z1);
                        *(uint32_t*)(smem + SM_ZH + o1) = packh2(z2, z3);
                    } else {
                        float2 wv = *(const float2*)&wos[c0];
                        os[mt * 2 + 0] = fmaf(z0, wv.x, fmaf(z1, wv.y, os[mt * 2 + 0]));
                        os[mt * 2 + 1] = fmaf(z2, wv.x, fmaf(z3, wv.y, os[mt * 2 + 1]));
                    }
                }
        }

        // ---- E2: fa for next layer (shift l+2, buf sbuf), seeded with fb ----
        if (l < DEPTH - 1) {
            uint32_t Yh[2][4];
            uint32_t yb = sb + SM_YB + sbuf * YBUF;
            uint32_t ft = sb + SM_FT + sbuf * FBUF;
            const float* fbp2 = (const float*)(smem + SM_FBB) + sbuf * TP;
            #pragma unroll
            for (int mt = 0; mt < 2; ++mt) {
                uint32_t ro = (uint32_t)(m0w + mt * 16 + (int)aRow) * 48 + aK8 * 2;
                ldsm4(Yh[mt], yb + ro);
            }
            #pragma unroll
            for (int nt = 0; nt < 4; ++nt) {
                uint32_t fo = (uint32_t)(n0w + nt * 8 + (int)fRow) * 48 + fK8 * 2;
                uint32_t Fh[2];
                ldsm2(Fh, ft + fo);
                float2 fbv = *(const float2*)&fbp2[n0w + nt * 8 + eCol];
                #pragma unroll
                for (int mt = 0; mt < 2; ++mt) {
                    fa[mt][nt][0] = fbv.x; fa[mt][nt][1] = fbv.y;
                    fa[mt][nt][2] = fbv.x; fa[mt][nt][3] = fbv.y;
                    mma16816(fa[mt][nt], Yh[mt], Fh);
                }
            }
        }

        // ---- G: W[l+1] landed; publish Z/buffers ----
        CP_WAIT(0);
        __syncthreads();
    }

    // ---- output reduce: 4 warpG partials ----
    {
        #pragma unroll
        for (int i = 0; i < 4; ++i) {
            os[i] += __shfl_xor_sync(0xffffffffu, os[i], 1);
            os[i] += __shfl_xor_sync(0xffffffffu, os[i], 2);
        }
        float* outp = (float*)(smem + SM_OUTP);
        if ((lane & 3) == 0) {
            #pragma unroll
            for (int mt = 0; mt < 2; ++mt) {
                outp[warpG * TP + m0w + mt * 16 + eRow]     = os[mt * 2 + 0];
                outp[warpG * TP + m0w + mt * 16 + 8 + eRow] = os[mt * 2 + 1];
            }
        }
        __syncthreads();
        if (tid < TP)
            out[pt0 + tid] = outp[tid] + outp[TP + tid] + outp[2 * TP + tid] +
                             outp[3 * TP + tid] + *bout;
    }
}

// ---------------------------------------------------------------------------
extern "C" void kernel_launch(void* const* d_in, const int* in_sizes, int n_in,
                              void* d_out, int out_size) {
    const float* x     = (const float*)d_in[0];
    const float* a     = (const float*)d_in[1];
    const float* Wftr  = (const float*)d_in[2];
    const float* bftr  = (const float*)d_in[3];
    const float* Wfwd  = (const float*)d_in[4];
    const float* bfwd  = (const float*)d_in[5];
    const float* Wcode = (const float*)d_in[6];
    const float* bcode = (const float*)d_in[7];
    const float* Wout  = (const float*)d_in[8];
    const float* bout  = (const float*)d_in[9];
    float* out = (float*)d_out;

    prep_all<<<NCODE_BLK + NW_BLK, 256>>>(a, Wcode, bcode, Wfwd, Wftr);

    cudaFuncSetAttribute(sinr_mma, cudaFuncAttributeMaxDynamicSharedMemorySize,
                         SM_TOTAL);
    sinr_mma<<<TOTAL_PTS / TP, NTHR, SM_TOTAL>>>(x, bftr, bfwd, Wout, bout, out);

    if (out_size >= TOTAL_PTS + in_sizes[0]) {
        cudaMemcpyAsync(out + TOTAL_PTS, x, (size_t)in_sizes[0] * sizeof(float),
                        cudaMemcpyDeviceToDevice);
    }
}